// round 1
// baseline (speedup 1.0000x reference)
#include <cuda_runtime.h>

#define NN 1500
#define MAXD 512
#define GO 8
#define HID 128
#define ALPHA 0.2f

// ---------------- scratch (device globals; no allocation allowed) ----------
__device__ int   g_col[NN * MAXD];
__device__ float g_val[NN * MAXD];
__device__ int   g_deg[NN];
__device__ float g_h[NN * GO];
__device__ float g_fs[NN];
__device__ float g_fd[NN];
__device__ float g_encA[NN * GO];
__device__ float g_encB[NN * GO];
__device__ float g_Apre[NN * HID];
__device__ float g_Bpre[NN * HID];

// ---------------- CSR build: one warp per row, ordered compaction ----------
__global__ void k_csr(const float* __restrict__ geo, const float* __restrict__ sem) {
    int warp = (blockIdx.x * blockDim.x + threadIdx.x) >> 5;
    int lane = threadIdx.x & 31;
    if (warp >= NN) return;
    const float* grow = geo + (size_t)warp * NN;
    const float* srow = sem + (size_t)warp * NN;
    int cnt = 0;
    for (int base = 0; base < NN; base += 32) {
        int j = base + lane;
        float v = 0.f;
        if (j < NN) v = grow[j] + srow[j];
        bool act = (j < NN) && (v > 0.f);
        unsigned m = __ballot_sync(0xffffffffu, act);
        if (act) {
            int pos = cnt + __popc(m & ((1u << lane) - 1u));
            if (pos < MAXD) {
                g_col[warp * MAXD + pos] = j;
                g_val[warp * MAXD + pos] = v;
            }
        }
        cnt += __popc(m);
    }
    if (lane == 0) g_deg[warp] = (cnt < MAXD) ? cnt : MAXD;
}

// ---------------- per-layer: h = enc @ W, fsrc/fdst = h @ a halves --------
__global__ void k_feat(int src, const float* __restrict__ feat0, int in_dim,
                       const float* __restrict__ W, const float* __restrict__ a) {
    int i = blockIdx.x * blockDim.x + threadIdx.x;
    if (i >= NN) return;
    const float* enc = (src == 0) ? feat0 : (src == 1 ? g_encA : g_encB);
    const float* er = enc + (size_t)i * in_dim;
    float h[GO];
    #pragma unroll
    for (int o = 0; o < GO; o++) {
        float s = 0.f;
        for (int c = 0; c < in_dim; c++) s += er[c] * W[c * GO + o];
        h[o] = s;
        g_h[i * GO + o] = s;
    }
    float fs = 0.f, fd = 0.f;
    #pragma unroll
    for (int o = 0; o < GO; o++) {
        fs += h[o] * a[o];
        fd += h[o] * a[GO + o];
    }
    g_fs[i] = fs;
    g_fd[i] = fd;
}

// ---------------- sparse masked softmax + aggregation + ELU ---------------
// one warp per row; dst: 1 -> g_encA, 2 -> g_encB
__global__ void k_gat(int dst) {
    __shared__ float sh_e[8][MAXD];
    int wrp  = threadIdx.x >> 5;
    int lane = threadIdx.x & 31;
    int row = blockIdx.x * 8 + wrp;
    if (row >= NN) return;
    int deg = g_deg[row];
    float fs = g_fs[row];

    float mmax = -1e30f;
    for (int t = lane; t < deg; t += 32) {
        int c = g_col[row * MAXD + t];
        float v = g_val[row * MAXD + t];
        float x = fs + g_fd[c];
        x = (x >= 0.f) ? x : ALPHA * x;
        float e = x * v;
        sh_e[wrp][t] = e;
        mmax = fmaxf(mmax, e);
    }
    #pragma unroll
    for (int o = 16; o > 0; o >>= 1)
        mmax = fmaxf(mmax, __shfl_xor_sync(0xffffffffu, mmax, o));

    __syncwarp();
    float sum = 0.f;
    float a0 = 0.f, a1 = 0.f, a2 = 0.f, a3 = 0.f, a4 = 0.f, a5 = 0.f, a6 = 0.f, a7 = 0.f;
    for (int t = lane; t < deg; t += 32) {
        int c = g_col[row * MAXD + t];
        float p = __expf(sh_e[wrp][t] - mmax);
        sum += p;
        const float* hc = g_h + c * GO;
        a0 += p * hc[0]; a1 += p * hc[1]; a2 += p * hc[2]; a3 += p * hc[3];
        a4 += p * hc[4]; a5 += p * hc[5]; a6 += p * hc[6]; a7 += p * hc[7];
    }
    #pragma unroll
    for (int o = 16; o > 0; o >>= 1) {
        sum += __shfl_xor_sync(0xffffffffu, sum, o);
        a0 += __shfl_xor_sync(0xffffffffu, a0, o);
        a1 += __shfl_xor_sync(0xffffffffu, a1, o);
        a2 += __shfl_xor_sync(0xffffffffu, a2, o);
        a3 += __shfl_xor_sync(0xffffffffu, a3, o);
        a4 += __shfl_xor_sync(0xffffffffu, a4, o);
        a5 += __shfl_xor_sync(0xffffffffu, a5, o);
        a6 += __shfl_xor_sync(0xffffffffu, a6, o);
        a7 += __shfl_xor_sync(0xffffffffu, a7, o);
    }
    if (lane == 0) {
        float* out = ((dst == 1) ? g_encA : g_encB) + row * GO;
        float inv = 1.f / sum;
        float r[GO] = {a0, a1, a2, a3, a4, a5, a6, a7};
        #pragma unroll
        for (int o = 0; o < GO; o++) {
            float x = r[o] * inv;
            out[o] = (x > 0.f) ? x : (__expf(x) - 1.f);
        }
    }
}

// ---------------- precompute A[i,k], B[j,k] (final enc in g_encA) ---------
__global__ void k_pre(const float* __restrict__ fc1w, const float* __restrict__ fc1b) {
    int t = blockIdx.x * blockDim.x + threadIdx.x;
    if (t >= NN * HID) return;
    int i = t / HID, k = t % HID;
    const float* enc = g_encA + i * GO;
    float sa = fc1b[k], sb = 0.f;
    #pragma unroll
    for (int c = 0; c < GO; c++) {
        sa += enc[c] * fc1w[c * HID + k];
        sb += enc[c] * fc1w[(GO + c) * HID + k];
    }
    g_Apre[t] = sa;
    g_Bpre[t] = sb;
}

// ---------------- pairwise MLP: out[i*N+j] --------------------------------
#define TI 32
#define TJ 32
__global__ void k_mlp(const float* __restrict__ dist,
                      const float* __restrict__ fc1w,
                      const float* __restrict__ fc2w,
                      const float* __restrict__ fc2b,
                      float* __restrict__ out) {
    __shared__ float As[HID][TI + 1];
    __shared__ float Bs[HID][TJ + 1];
    __shared__ float swd[HID], sw2[HID];
    int i0 = blockIdx.y * TI;
    int j0 = blockIdx.x * TJ;
    int tid = threadIdx.x;  // 256 threads

    for (int l = tid; l < TI * HID; l += 256) {
        int k = l % HID, r = l / HID;
        int i = i0 + r;
        As[k][r] = (i < NN) ? g_Apre[i * HID + k] : 0.f;
        int j = j0 + r;
        Bs[k][r] = (j < NN) ? g_Bpre[j * HID + k] : 0.f;
    }
    for (int l = tid; l < HID; l += 256) {
        swd[l] = fc1w[2 * GO * HID + l];   // row 16 of fc1_w
        sw2[l] = fc2w[l];
    }
    __syncthreads();

    int tj = tid & 31;
    int ig = tid >> 5;       // 0..7
    int j = j0 + tj;

    float acc[4] = {0.f, 0.f, 0.f, 0.f};
    float dv[4];
    #pragma unroll
    for (int r = 0; r < 4; r++) {
        int ii = i0 + ig + 8 * r;
        dv[r] = (ii < NN && j < NN) ? dist[(size_t)ii * NN + j] : 0.f;
    }

    #pragma unroll 4
    for (int k = 0; k < HID; k++) {
        float b = Bs[k][tj];
        float wd = swd[k];
        float w2 = sw2[k];
        #pragma unroll
        for (int r = 0; r < 4; r++) {
            float t = As[k][ig + 8 * r] + b + dv[r] * wd;
            t = fmaxf(t, 0.f);
            acc[r] += t * w2;
        }
    }

    float bias = fc2b[0];
    #pragma unroll
    for (int r = 0; r < 4; r++) {
        int ii = i0 + ig + 8 * r;
        if (ii < NN && j < NN) out[(size_t)ii * NN + j] = acc[r] + bias;
    }
}

// ---------------- launch ---------------------------------------------------
extern "C" void kernel_launch(void* const* d_in, const int* in_sizes, int n_in,
                              void* d_out, int out_size) {
    const float* geo   = (const float*)d_in[0];
    const float* sem   = (const float*)d_in[1];
    const float* feat  = (const float*)d_in[2];
    // d_in[3] region_pairs (int64) == meshgrid(i,j) flattened row-major; i = p/N, j = p%N
    const float* dist  = (const float*)d_in[4];
    const float* W0    = (const float*)d_in[5];
    const float* W1    = (const float*)d_in[6];
    const float* W2    = (const float*)d_in[7];
    const float* a0    = (const float*)d_in[8];
    const float* a1    = (const float*)d_in[9];
    const float* a2    = (const float*)d_in[10];
    const float* fc1w  = (const float*)d_in[11];
    const float* fc1b  = (const float*)d_in[12];
    const float* fc2w  = (const float*)d_in[13];
    const float* fc2b  = (const float*)d_in[14];
    float* out = (float*)d_out;

    k_csr<<<(NN * 32 + 255) / 256, 256>>>(geo, sem);

    k_feat<<<(NN + 255) / 256, 256>>>(0, feat, 32, W0, a0);
    k_gat<<<(NN + 7) / 8, 256>>>(1);

    k_feat<<<(NN + 255) / 256, 256>>>(1, feat, GO, W1, a1);
    k_gat<<<(NN + 7) / 8, 256>>>(2);

    k_feat<<<(NN + 255) / 256, 256>>>(2, feat, GO, W2, a2);
    k_gat<<<(NN + 7) / 8, 256>>>(1);

    k_pre<<<(NN * HID + 255) / 256, 256>>>(fc1w, fc1b);

    dim3 grid((NN + TJ - 1) / TJ, (NN + TI - 1) / TI);
    k_mlp<<<grid, 256>>>(dist, fc1w, fc2w, fc2b, out);
}

// round 2
// speedup vs baseline: 1.5195x; 1.5195x over previous
#include <cuda_runtime.h>

#define NN 1500
#define MAXD 512
#define GO 8
#define HID 128
#define ALPHA 0.2f

typedef unsigned long long ull;

// ---------------- scratch (device globals; no allocation allowed) ----------
__device__ int   g_col[NN * MAXD];
__device__ float g_val[NN * MAXD];
__device__ int   g_deg[NN];
__device__ float g_h[NN * GO];
__device__ float g_fs[NN];
__device__ float g_fd[NN];
__device__ float g_encA[NN * GO];
__device__ float g_encB[NN * GO];
__device__ float g_Apre[NN * HID];
__device__ float g_Bpre[NN * HID];

// ---------------- f32x2 packed helpers (sm_103a) ---------------------------
__device__ __forceinline__ ull pk2(float lo, float hi) {
    ull r; asm("mov.b64 %0, {%1, %2};" : "=l"(r) : "f"(lo), "f"(hi)); return r;
}
__device__ __forceinline__ ull fma2_(ull a, ull b, ull c) {
    ull d; asm("fma.rn.f32x2 %0, %1, %2, %3;" : "=l"(d) : "l"(a), "l"(b), "l"(c)); return d;
}
__device__ __forceinline__ ull add2_(ull a, ull b) {
    ull d; asm("add.rn.f32x2 %0, %1, %2;" : "=l"(d) : "l"(a), "l"(b)); return d;
}
__device__ __forceinline__ ull relu2_(ull t) {
    ull r;
    asm("{.reg .f32 l, h;\n\t"
        "mov.b64 {l, h}, %1;\n\t"
        "max.f32 l, l, 0f00000000;\n\t"
        "max.f32 h, h, 0f00000000;\n\t"
        "mov.b64 %0, {l, h};}" : "=l"(r) : "l"(t));
    return r;
}
__device__ __forceinline__ void upk2(ull v, float& lo, float& hi) {
    asm("mov.b64 {%0, %1}, %2;" : "=f"(lo), "=f"(hi) : "l"(v));
}

// ---------------- CSR build: one warp per row, ordered compaction ----------
__global__ void k_csr(const float* __restrict__ geo, const float* __restrict__ sem) {
    int warp = (blockIdx.x * blockDim.x + threadIdx.x) >> 5;
    int lane = threadIdx.x & 31;
    if (warp >= NN) return;
    const float* grow = geo + (size_t)warp * NN;
    const float* srow = sem + (size_t)warp * NN;
    int cnt = 0;
    for (int base = 0; base < NN; base += 32) {
        int j = base + lane;
        float v = 0.f;
        if (j < NN) v = grow[j] + srow[j];
        bool act = (j < NN) && (v > 0.f);
        unsigned m = __ballot_sync(0xffffffffu, act);
        if (act) {
            int pos = cnt + __popc(m & ((1u << lane) - 1u));
            if (pos < MAXD) {
                g_col[warp * MAXD + pos] = j;
                g_val[warp * MAXD + pos] = v;
            }
        }
        cnt += __popc(m);
    }
    if (lane == 0) g_deg[warp] = (cnt < MAXD) ? cnt : MAXD;
}

// ---------------- per-layer: warp per row, lane-parallel over in_dim -------
__global__ void k_feat(int src, const float* __restrict__ feat0, int in_dim,
                       const float* __restrict__ W, const float* __restrict__ a) {
    int w = (blockIdx.x * blockDim.x + threadIdx.x) >> 5;
    int lane = threadIdx.x & 31;
    if (w >= NN) return;
    const float* enc = (src == 0) ? feat0 : (src == 1 ? g_encA : g_encB);
    float ev = (lane < in_dim) ? enc[(size_t)w * in_dim + lane] : 0.f;
    float part[GO];
    #pragma unroll
    for (int o = 0; o < GO; o++)
        part[o] = (lane < in_dim) ? ev * W[lane * GO + o] : 0.f;
    #pragma unroll
    for (int o = 0; o < GO; o++) {
        #pragma unroll
        for (int s = 16; s > 0; s >>= 1)
            part[o] += __shfl_xor_sync(0xffffffffu, part[o], s);
    }
    if (lane < GO) g_h[w * GO + lane] = part[lane];
    float fs = 0.f, fd = 0.f;
    #pragma unroll
    for (int o = 0; o < GO; o++) { fs += part[o] * a[o]; fd += part[o] * a[GO + o]; }
    if (lane == 0) { g_fs[w] = fs; g_fd[w] = fd; }
}

// ---------------- sparse masked softmax + aggregation + ELU ---------------
__global__ void k_gat(int dst) {
    __shared__ float sh_e[8][MAXD];
    int wrp  = threadIdx.x >> 5;
    int lane = threadIdx.x & 31;
    int row = blockIdx.x * 8 + wrp;
    if (row >= NN) return;
    int deg = g_deg[row];
    float fs = g_fs[row];

    float mmax = -1e30f;
    for (int t = lane; t < deg; t += 32) {
        int c = g_col[row * MAXD + t];
        float v = g_val[row * MAXD + t];
        float x = fs + g_fd[c];
        x = (x >= 0.f) ? x : ALPHA * x;
        float e = x * v;
        sh_e[wrp][t] = e;
        mmax = fmaxf(mmax, e);
    }
    #pragma unroll
    for (int o = 16; o > 0; o >>= 1)
        mmax = fmaxf(mmax, __shfl_xor_sync(0xffffffffu, mmax, o));

    __syncwarp();
    float sum = 0.f;
    float a0 = 0.f, a1 = 0.f, a2 = 0.f, a3 = 0.f, a4 = 0.f, a5 = 0.f, a6 = 0.f, a7 = 0.f;
    for (int t = lane; t < deg; t += 32) {
        int c = g_col[row * MAXD + t];
        float p = __expf(sh_e[wrp][t] - mmax);
        sum += p;
        const float* hc = g_h + c * GO;
        a0 += p * hc[0]; a1 += p * hc[1]; a2 += p * hc[2]; a3 += p * hc[3];
        a4 += p * hc[4]; a5 += p * hc[5]; a6 += p * hc[6]; a7 += p * hc[7];
    }
    #pragma unroll
    for (int o = 16; o > 0; o >>= 1) {
        sum += __shfl_xor_sync(0xffffffffu, sum, o);
        a0 += __shfl_xor_sync(0xffffffffu, a0, o);
        a1 += __shfl_xor_sync(0xffffffffu, a1, o);
        a2 += __shfl_xor_sync(0xffffffffu, a2, o);
        a3 += __shfl_xor_sync(0xffffffffu, a3, o);
        a4 += __shfl_xor_sync(0xffffffffu, a4, o);
        a5 += __shfl_xor_sync(0xffffffffu, a5, o);
        a6 += __shfl_xor_sync(0xffffffffu, a6, o);
        a7 += __shfl_xor_sync(0xffffffffu, a7, o);
    }
    if (lane == 0) {
        float* out = ((dst == 1) ? g_encA : g_encB) + row * GO;
        float inv = 1.f / sum;
        float r[GO] = {a0, a1, a2, a3, a4, a5, a6, a7};
        #pragma unroll
        for (int o = 0; o < GO; o++) {
            float x = r[o] * inv;
            out[o] = (x > 0.f) ? x : (__expf(x) - 1.f);
        }
    }
}

// ---------------- precompute A[i,k] (with bias), B[j,k] --------------------
__global__ void k_pre(const float* __restrict__ fc1w, const float* __restrict__ fc1b) {
    int t = blockIdx.x * blockDim.x + threadIdx.x;
    if (t >= NN * HID) return;
    int i = t / HID, k = t % HID;
    const float* enc = g_encA + i * GO;
    float sa = fc1b[k], sb = 0.f;
    #pragma unroll
    for (int c = 0; c < GO; c++) {
        sa += enc[c] * fc1w[c * HID + k];
        sb += enc[c] * fc1w[(GO + c) * HID + k];
    }
    g_Apre[t] = sa;
    g_Bpre[t] = sb;
}

// ---------------- pairwise MLP: out[i*N+j], f32x2 packed -------------------
// tile: 64 i-rows x 32 j-cols; 256 threads; thread = (ig 0..7) x (tj 0..31)
// each thread: 8 i-rows = 4 packed pairs, 1 j.
// dynamic smem:
//   as_p  [32 pairs][HID] float2 interleaved: (A[2p][k], A[2p+1][k])  -> 32 KB
//   bst   [32][HID+4] floats (row stride 132)                         -> 16.5 KB
//   wz    [HID] float4 = (wd,wd,w2,w2)                                -> 2 KB
#define MLP_SMEM_FLOATS (8192 + 32 * 132 + 512)
#define MLP_SMEM_BYTES  (MLP_SMEM_FLOATS * 4)

__global__ void __launch_bounds__(256) k_mlp(
        const float* __restrict__ dist,
        const float* __restrict__ fc1w,
        const float* __restrict__ fc2w,
        const float* __restrict__ fc2b,
        float* __restrict__ out) {
    extern __shared__ float smem[];
    float* as_p = smem;                  // 8192 floats
    float* bst  = smem + 8192;           // 32*132 floats
    float* wz   = smem + 8192 + 32 * 132; // 512 floats (128 x float4)

    int i0 = blockIdx.y * 64;
    int j0 = blockIdx.x * 32;
    int tid = threadIdx.x;

    // fill as_p: float2 per (pair p, k): rows (i0+2p, i0+2p+1)
    {
        float2* ap2 = (float2*)as_p;
        for (int l = tid; l < 32 * HID; l += 256) {
            int p = l >> 7;          // 0..31
            int k = l & 127;
            int r0 = i0 + 2 * p;
            float lo = (r0     < NN) ? g_Apre[r0 * HID + k]       : 0.f;
            float hi = (r0 + 1 < NN) ? g_Apre[(r0 + 1) * HID + k] : 0.f;
            ap2[p * HID + k] = make_float2(lo, hi);
        }
        for (int l = tid; l < 32 * HID; l += 256) {
            int t = l >> 7;          // j within tile
            int k = l & 127;
            int j = j0 + t;
            bst[t * 132 + k] = (j < NN) ? g_Bpre[j * HID + k] : 0.f;
        }
        if (tid < HID) {
            float wd = fc1w[2 * GO * HID + tid];
            float w2 = fc2w[tid];
            ((float4*)wz)[tid] = make_float4(wd, wd, w2, w2);
        }
    }
    __syncthreads();

    int tj = tid & 31;
    int ig = tid >> 5;
    int jg = j0 + tj;

    // distance values for the 8 rows, packed into 4 pairs
    ull dv2[4];
    #pragma unroll
    for (int q = 0; q < 4; q++) {
        int ia = i0 + ig * 8 + 2 * q;
        float lo = (ia     < NN && jg < NN) ? dist[(size_t)ia * NN + jg]       : 0.f;
        float hi = (ia + 1 < NN && jg < NN) ? dist[(size_t)(ia + 1) * NN + jg] : 0.f;
        dv2[q] = pk2(lo, hi);
    }

    ull acc[4] = {0ull, 0ull, 0ull, 0ull};

    const ulonglong2* ap[4];
    #pragma unroll
    for (int q = 0; q < 4; q++)
        ap[q] = (const ulonglong2*)(as_p + (ig * 4 + q) * (2 * HID));
    const float4* brow = (const float4*)(bst + tj * 132);
    const ulonglong2* wzp = (const ulonglong2*)wz;

    #pragma unroll 2
    for (int k = 0; k < HID; k += 4) {
        float4 bq = brow[k >> 2];
        ulonglong2 av0[4], av1[4];
        #pragma unroll
        for (int q = 0; q < 4; q++) {
            av0[q] = ap[q][(k >> 1)];      // packed pairs for k, k+1
            av1[q] = ap[q][(k >> 1) + 1];  // packed pairs for k+2, k+3
        }
        float bks[4] = {bq.x, bq.y, bq.z, bq.w};
        #pragma unroll
        for (int kk = 0; kk < 4; kk++) {
            ulonglong2 wv = wzp[k + kk];   // .x = (wd,wd), .y = (w2,w2)
            ull b2 = pk2(bks[kk], bks[kk]);
            #pragma unroll
            for (int q = 0; q < 4; q++) {
                ull a2 = (kk < 2) ? ((kk & 1) ? av0[q].y : av0[q].x)
                                  : ((kk & 1) ? av1[q].y : av1[q].x);
                ull t = add2_(fma2_(dv2[q], wv.x, b2), a2);
                acc[q] = fma2_(relu2_(t), wv.y, acc[q]);
            }
        }
    }

    float bias = fc2b[0];
    if (jg < NN) {
        #pragma unroll
        for (int q = 0; q < 4; q++) {
            float s0, s1;
            upk2(acc[q], s0, s1);
            int ia = i0 + ig * 8 + 2 * q;
            if (ia     < NN) out[(size_t)ia * NN + jg]       = s0 + bias;
            if (ia + 1 < NN) out[(size_t)(ia + 1) * NN + jg] = s1 + bias;
        }
    }
}

// ---------------- launch ---------------------------------------------------
extern "C" void kernel_launch(void* const* d_in, const int* in_sizes, int n_in,
                              void* d_out, int out_size) {
    const float* geo   = (const float*)d_in[0];
    const float* sem   = (const float*)d_in[1];
    const float* feat  = (const float*)d_in[2];
    // d_in[3] region_pairs (int64) == meshgrid flattened row-major; i = p/N, j = p%N
    const float* dist  = (const float*)d_in[4];
    const float* W0    = (const float*)d_in[5];
    const float* W1    = (const float*)d_in[6];
    const float* W2    = (const float*)d_in[7];
    const float* a0    = (const float*)d_in[8];
    const float* a1    = (const float*)d_in[9];
    const float* a2    = (const float*)d_in[10];
    const float* fc1w  = (const float*)d_in[11];
    const float* fc1b  = (const float*)d_in[12];
    const float* fc2w  = (const float*)d_in[13];
    const float* fc2b  = (const float*)d_in[14];
    float* out = (float*)d_out;

    cudaFuncSetAttribute(k_mlp, cudaFuncAttributeMaxDynamicSharedMemorySize,
                         MLP_SMEM_BYTES);

    k_csr<<<(NN * 32 + 255) / 256, 256>>>(geo, sem);

    k_feat<<<(NN * 32 + 255) / 256, 256>>>(0, feat, 32, W0, a0);
    k_gat<<<(NN + 7) / 8, 256>>>(1);

    k_feat<<<(NN * 32 + 255) / 256, 256>>>(1, feat, GO, W1, a1);
    k_gat<<<(NN + 7) / 8, 256>>>(2);

    k_feat<<<(NN * 32 + 255) / 256, 256>>>(2, feat, GO, W2, a2);
    k_gat<<<(NN + 7) / 8, 256>>>(1);

    k_pre<<<(NN * HID + 255) / 256, 256>>>(fc1w, fc1b);

    dim3 grid((NN + 31) / 32, (NN + 63) / 64);
    k_mlp<<<grid, 256, MLP_SMEM_BYTES>>>(dist, fc1w, fc2w, fc2b, out);
}